// round 7
// baseline (speedup 1.0000x reference)
#include <cuda_runtime.h>
#include <math.h>
#include <stdint.h>

#define B    4
#define N    16384
#define CIN  4
#define SD   3
#define W    256
#define L    8
#define M    32
#define H    8
#define FF   1024
#define TF   4
#define DH   32
#define TOK1 32
#define TOKF 128

__device__ float g_x[(size_t)B * N * W];
__device__ float g_w[(size_t)B * N * M];
__device__ float g_z[(size_t)L * B * M * W];     // per-layer (zeroed once per launch)
__device__ float g_wsum[L * B * M];
__device__ float g_zp[B * M * W];
__device__ float g_w1t[(size_t)L * FF * W];      // [L][FF][Wperm] tf32
__device__ float g_w2t[(size_t)L * W * FF];      // [L][W][FFperm] tf32

// ---------- helpers ----------
__device__ __forceinline__ float to_tf32(float x) {
    uint32_t r; asm("cvt.rna.tf32.f32 %0, %1;" : "=r"(r) : "f"(x));
    return __uint_as_float(r);
}
__device__ __forceinline__ int kperm(int k) {
    return (k & ~7) | ((k & 3) << 1) | ((k >> 2) & 1);
}
__device__ __forceinline__ int swz(int r, int k, int S) {
    return r * S + ((((k >> 3) ^ (r & 7)) << 3) | ((k & 3) << 1) | ((k >> 2) & 1));
}
__device__ __forceinline__ void mma8(float* d, const uint32_t* a, const uint32_t* b) {
    asm volatile("mma.sync.aligned.m16n8k8.row.col.f32.tf32.tf32.f32 "
        "{%0,%1,%2,%3}, {%4,%5,%6,%7}, {%8,%9}, {%0,%1,%2,%3};"
        : "+f"(d[0]), "+f"(d[1]), "+f"(d[2]), "+f"(d[3])
        : "r"(a[0]), "r"(a[1]), "r"(a[2]), "r"(a[3]), "r"(b[0]), "r"(b[1]));
}

// ---------------- K0: embed (16 tokens / block) ----------------
__global__ void __launch_bounds__(256) embed_kernel(
    const float* __restrict__ feat, const float* __restrict__ coords,
    const float* __restrict__ tn, const float* __restrict__ ew, const float* __restrict__ eb)
{
    __shared__ float f[16][16];
    int t0 = blockIdx.x * 16;
    int tid = threadIdx.x;
    {
        int t = tid >> 4, k = tid & 15;
        int token = t0 + t, b = token / N;
        float v = 0.f;
        if (k < CIN) v = feat[(size_t)token * CIN + k];
        else if (k < CIN + SD) v = coords[(size_t)token * SD + (k - CIN)];
        else if (k < 15) {
            int kk = k - 7, i = kk & 3;
            float ang = powf(1000.0f, -(float)i / (float)TF) * (tn[b] * 1000.0f);
            v = (kk < TF) ? sinf(ang) : cosf(ang);
        }
        f[t][k] = v;
    }
    __syncthreads();
    int c = tid;
    float wreg[15];
#pragma unroll
    for (int k = 0; k < 15; k++) wreg[k] = ew[k * W + c];
    float bias = eb[c];
#pragma unroll 4
    for (int t = 0; t < 16; t++) {
        float acc = bias;
#pragma unroll
        for (int k = 0; k < 15; k++) acc += f[t][k] * wreg[k];
        g_x[(size_t)(t0 + t) * W + c] = acc;
    }
}

// ---------------- weight transform + zero (fused) ----------------
__global__ void __launch_bounds__(256) w1t_kernel(const float* __restrict__ f1w)
{
    int idx = blockIdx.x * 256 + threadIdx.x;            // L*FF*W
    int l = idx / (FF * W), r = idx % (FF * W), j = r / W, c = r % W;
    g_w1t[((size_t)l * FF + j) * W + kperm(c)] =
        to_tf32(f1w[((size_t)l * W + c) * FF + j]);
}
#define NB_W2T (L * W * FF / 256)
#define NB_Z   (L * B * M * W / 256)
__global__ void __launch_bounds__(256) w2t_zero_kernel(const float* __restrict__ f2w)
{
    int bid = blockIdx.x;
    if (bid < NB_W2T) {
        int idx = bid * 256 + threadIdx.x;
        int l = idx / (W * FF), r = idx % (W * FF), c = r / FF, j = r % FF;
        g_w2t[((size_t)l * W + c) * FF + kperm(j)] =
            to_tf32(f2w[((size_t)l * FF + j) * W + c]);
    } else if (bid < NB_W2T + NB_Z) {
        int idx = (bid - NB_W2T) * 256 + threadIdx.x;
        g_z[idx] = 0.f;
    } else {
        for (int i = threadIdx.x; i < L * B * M; i += 256) g_wsum[i] = 0.f;
    }
}

// ---------------- K1: slice ----------------
__global__ void __launch_bounds__(256) slice_kernel(
    const float* __restrict__ ln_g, const float* __restrict__ ln_b,
    const float* __restrict__ sw, const float* __restrict__ sb, int layer)
{
    __shared__ float hs[TOK1][W];
    __shared__ float ws[TOK1][M];
    __shared__ float inv[TOK1];
    int nb = N / TOK1, b = blockIdx.x / nb, t0 = (blockIdx.x % nb) * TOK1;
    int tid = threadIdx.x, warp = tid >> 5, lane = tid & 31;
    const float* g = ln_g + layer * W;
    const float* be = ln_b + layer * W;
    float* zdst = g_z + (size_t)layer * B * M * W;
    float* wsdst = g_wsum + layer * B * M;

    for (int t = warp; t < TOK1; t += 8) {
        const float* xr = g_x + ((size_t)(b * N + t0 + t)) * W;
        float v[8]; float s = 0.f, s2 = 0.f;
#pragma unroll
        for (int i = 0; i < 8; i++) { v[i] = xr[lane + 32 * i]; s += v[i]; s2 += v[i] * v[i]; }
#pragma unroll
        for (int o = 16; o > 0; o >>= 1) {
            s += __shfl_xor_sync(0xffffffffu, s, o);
            s2 += __shfl_xor_sync(0xffffffffu, s2, o);
        }
        float mean = s * (1.0f / W), var = s2 * (1.0f / W) - mean * mean;
        float r = rsqrtf(var + 1e-5f);
#pragma unroll
        for (int i = 0; i < 8; i++) {
            int c = lane + 32 * i;
            hs[t][c] = (v[i] - mean) * r * g[c] + be[c];
        }
    }
    __syncthreads();
    const float* swl = sw + (size_t)layer * W * M;
    float lg[4];
#pragma unroll
    for (int r = 0; r < 4; r++) {
        int idx = tid + 256 * r, t = idx / M, m = idx % M;
        float acc = sb[layer * M + m];
#pragma unroll 8
        for (int c = 0; c < W; c++) acc += hs[t][c] * swl[c * M + m];
        lg[r] = acc;
    }
#pragma unroll
    for (int r = 0; r < 4; r++) { int idx = tid + 256 * r; ws[idx / M][idx % M] = lg[r]; }
    __syncthreads();
    if (tid < TOK1) {
        float mx = -1e30f;
#pragma unroll
        for (int m = 0; m < M; m++) mx = fmaxf(mx, ws[tid][m]);
        float sum = 0.f;
#pragma unroll
        for (int m = 0; m < M; m++) { float e = expf(ws[tid][m] - mx); ws[tid][m] = e; sum += e; }
        inv[tid] = 1.0f / sum;
    }
    __syncthreads();
#pragma unroll
    for (int r = 0; r < 4; r++) {
        int idx = tid + 256 * r, t = idx / M, m = idx % M;
        float v = ws[t][m] * inv[t];
        ws[t][m] = v;
        g_w[((size_t)(b * N + t0 + t)) * M + m] = v;
    }
    __syncthreads();
    if (tid < M) {
        float s = 0.f;
#pragma unroll
        for (int t = 0; t < TOK1; t++) s += ws[t][tid];
        atomicAdd(&wsdst[b * M + tid], s);
    }
    float zacc[M];
#pragma unroll
    for (int m = 0; m < M; m++) zacc[m] = 0.f;
    for (int t = 0; t < TOK1; t++) {
        float hv = hs[t][tid];
#pragma unroll
        for (int m = 0; m < M; m++) zacc[m] += ws[t][m] * hv;
    }
#pragma unroll
    for (int m = 0; m < M; m++) atomicAdd(&zdst[(b * M + m) * W + tid], zacc[m]);
}

// ---------------- K2: fused latent (qkv + attn + zp), one block per b ------
#define LAT_SMEM ((M * W + M * 3 * W + M * W) * 4)
__global__ void __launch_bounds__(512, 1) latent_kernel(
    const float* __restrict__ qkvw, const float* __restrict__ qkvb,
    const float* __restrict__ ow, const float* __restrict__ ob, int layer)
{
    extern __shared__ float ls[];
    float* zs = ls;                 // [32][256]
    float* qk = ls + M * W;         // [32][768]
    float* os = qk + M * 3 * W;     // [32][256]
    int b = blockIdx.x;
    int tid = threadIdx.x, warp = tid >> 5, lane = tid & 31;

    const float* zsrc = g_z + (size_t)layer * B * M * W + (size_t)b * M * W;
    const float* wsv = g_wsum + layer * B * M + b * M;
    for (int i = tid; i < M * W; i += 512) {
        int m = i >> 8;
        zs[i] = zsrc[i] / fmaxf(wsv[m], 1e-8f);
    }
    __syncthreads();

    const float* wq = qkvw + (size_t)layer * W * 3 * W;
    const float* bq = qkvb + layer * 3 * W;
    for (int i = tid; i < M * 3 * W; i += 512) {
        int m = i / (3 * W), j = i % (3 * W);
        float acc = bq[j];
        const float* zrow = zs + m * W;
#pragma unroll 8
        for (int c = 0; c < W; c++) acc += zrow[c] * wq[(size_t)c * (3 * W) + j];
        qk[i] = acc;
    }
    __syncthreads();

    if (warp < H) {
        int m = lane, h = warp;
        const float scale = 0.17677669529663687f;
        float qreg[DH], srow[M];
#pragma unroll
        for (int d = 0; d < DH; d++) qreg[d] = qk[m * (3 * W) + h * DH + d];
        float mx = -1e30f;
#pragma unroll
        for (int n = 0; n < M; n++) {
            float acc = 0.f;
#pragma unroll
            for (int d = 0; d < DH; d++) acc += qreg[d] * qk[n * (3 * W) + W + h * DH + d];
            acc *= scale;
            srow[n] = acc;
            mx = fmaxf(mx, acc);
        }
        float ssum = 0.f;
#pragma unroll
        for (int n = 0; n < M; n++) { srow[n] = expf(srow[n] - mx); ssum += srow[n]; }
        float is = 1.0f / ssum;
#pragma unroll
        for (int d = 0; d < DH; d++) {
            float acc = 0.f;
#pragma unroll
            for (int n = 0; n < M; n++) acc += srow[n] * qk[n * (3 * W) + 2 * W + h * DH + d];
            os[m * W + h * DH + d] = acc * is;
        }
    }
    __syncthreads();

    const float* wo = ow + (size_t)layer * W * W;
    const float* bo = ob + layer * W;
    for (int i = tid; i < M * W; i += 512) {
        int m = i >> 8, c = i & 255;
        float acc = bo[c];
        const float* orow = os + m * W;
#pragma unroll 8
        for (int k = 0; k < W; k++) acc += orow[k] * wo[(size_t)k * W + c];
        g_zp[(size_t)(b * M + m) * W + c] = acc;
    }
}

// ---------------- K3: FFN mma.sync tf32 (128 tok / 512 thr / 16 warps) -----
#define SMW_G  (TOKF * 256)
#define SM_FFN_BYTES ((TOKF * 256 + TOKF * 128) * 4)

__global__ void __launch_bounds__(512, 1) ffn_mma_kernel(
    const float* __restrict__ ln2g, const float* __restrict__ ln2b,
    const float* __restrict__ f1b, const float* __restrict__ f2b, int layer)
{
    extern __shared__ float sm[];
    float* s_h2 = sm;
    float* s_g  = sm + SMW_G;
    int tid = threadIdx.x;
    int warp = tid >> 5, lane = tid & 31, g = lane >> 2, tig = lane & 3;
    int nb = N / TOKF, b = blockIdx.x / nb, t0 = (blockIdx.x % nb) * TOKF;
    size_t xbase = ((size_t)(b * N) + t0) * W;

    // ---- prologue: x_mid = x + w@zp ----
    int c = tid & 255, half = tid >> 8;
    float zpc[M];
#pragma unroll
    for (int m = 0; m < M; m++) zpc[m] = g_zp[(size_t)(b * M + m) * W + c];
    for (int i = tid; i < TOKF * M; i += 512)
        s_g[i] = g_w[((size_t)(b * N) + t0 + i / M) * M + (i % M)];
    __syncthreads();
    for (int t = half * 64; t < half * 64 + 64; t++) {
        float acc = g_x[xbase + (size_t)t * W + c];
#pragma unroll
        for (int m = 0; m < M; m++) acc += s_g[t * M + m] * zpc[m];
        g_x[xbase + (size_t)t * W + c] = acc;     // keep x_mid for residual
        s_h2[swz(t, c, 256)] = acc;
    }
    __syncthreads();

    // ---- LN2 in place (tf32-rounded) ----
    {
        const float* g2 = ln2g + layer * W;
        const float* b2 = ln2b + layer * W;
        for (int rr = 0; rr < 8; rr++) {
            int r = warp * 8 + rr;
            float v[8]; float s = 0.f, s2 = 0.f;
#pragma unroll
            for (int i = 0; i < 8; i++) {
                v[i] = s_h2[swz(r, lane + 32 * i, 256)];
                s += v[i]; s2 += v[i] * v[i];
            }
#pragma unroll
            for (int o = 16; o > 0; o >>= 1) {
                s += __shfl_xor_sync(0xffffffffu, s, o);
                s2 += __shfl_xor_sync(0xffffffffu, s2, o);
            }
            float mean = s * (1.0f / W), var = s2 * (1.0f / W) - mean * mean;
            float rs = rsqrtf(var + 1e-5f);
#pragma unroll
            for (int i = 0; i < 8; i++) {
                int cc = lane + 32 * i;
                s_h2[swz(r, cc, 256)] = to_tf32((v[i] - mean) * rs * g2[cc] + b2[cc]);
            }
        }
    }
    __syncthreads();

    const float* w1l = g_w1t + (size_t)layer * FF * W;
    const float* w2l = g_w2t + (size_t)layer * W * FF;
    const float* b1l = f1b + layer * FF;

    int wm = warp >> 2, wn = warp & 3;       // 4x4 warp grid
    float d2[2][8][4];
#pragma unroll
    for (int mt = 0; mt < 2; mt++)
#pragma unroll
        for (int nt = 0; nt < 8; nt++)
#pragma unroll
            for (int q = 0; q < 4; q++) d2[mt][nt][q] = 0.f;

    for (int chunk = 0; chunk < 8; chunk++) {
        int j0 = chunk * 128;

        // ===== GEMM1: D1[128x128] = h2 @ W1T(j-chunk), K=256 =====
        float d1[2][4][4];
#pragma unroll
        for (int mt = 0; mt < 2; mt++)
#pragma unroll
            for (int nt = 0; nt < 4; nt++)
#pragma unroll
                for (int q = 0; q < 4; q++) d1[mt][nt][q] = 0.f;

#pragma unroll 4
        for (int ks = 0; ks < 32; ks++) {
            int kx = ((ks ^ g) << 3) + 2 * tig;
            uint32_t af[2][4];
#pragma unroll
            for (int mt = 0; mt < 2; mt++) {
                int r0 = wm * 32 + mt * 16 + g;
                float2 v0 = *(const float2*)&s_h2[r0 * 256 + kx];
                float2 v1 = *(const float2*)&s_h2[(r0 + 8) * 256 + kx];
                af[mt][0] = __float_as_uint(v0.x);
                af[mt][1] = __float_as_uint(v1.x);
                af[mt][2] = __float_as_uint(v0.y);
                af[mt][3] = __float_as_uint(v1.y);
            }
#pragma unroll
            for (int nt = 0; nt < 4; nt++) {
                int j = j0 + wn * 32 + nt * 8 + g;
                float2 bv = *(const float2*)&w1l[(size_t)j * W + ks * 8 + 2 * tig];
                uint32_t bf[2] = { __float_as_uint(bv.x), __float_as_uint(bv.y) };
                mma8(d1[0][nt], af[0], bf);
                mma8(d1[1][nt], af[1], bf);
            }
        }
        __syncthreads();

        // ===== bias + gelu -> G (tf32) =====
#pragma unroll
        for (int mt = 0; mt < 2; mt++) {
#pragma unroll
            for (int nt = 0; nt < 4; nt++) {
                int row = wm * 32 + mt * 16 + g;
                int jc = wn * 32 + nt * 8 + 2 * tig;
#pragma unroll
                for (int q = 0; q < 4; q++) {
                    int rr = row + (q >> 1) * 8;
                    int jj = jc + (q & 1);
                    float x = d1[mt][nt][q] + b1l[j0 + jj];
                    float gl = 0.5f * x * (1.0f + erff(x * 0.7071067811865476f));
                    s_g[swz(rr, jj, 128)] = to_tf32(gl);
                }
            }
        }
        __syncthreads();

        // ===== GEMM2 partial: D2[128x256] += G @ W2T(chunk), K=128 =====
#pragma unroll 2
        for (int ks = 0; ks < 16; ks++) {
            int kx = ((ks ^ g) << 3) + 2 * tig;
            uint32_t af[2][4];
#pragma unroll
            for (int mt = 0; mt < 2; mt++) {
                int r0 = wm * 32 + mt * 16 + g;
                float2 v0 = *(const float2*)&s_g[r0 * 128 + kx];
                float2 v1 = *(const float2*)&s_g[(r0 + 8) * 128 + kx];
                af[mt][0] = __float_as_uint(v0.x);
                af[mt][1] = __float_as_uint(v1.x);
                af[mt][2] = __float_as_uint(v0.y);
                af[mt][3] = __float_as_uint(v1.y);
            }
#pragma unroll
            for (int nt = 0; nt < 8; nt++) {
                int cc = wn * 64 + nt * 8 + g;
                float2 bv = *(const float2*)&w2l[(size_t)cc * FF + j0 + ks * 8 + 2 * tig];
                uint32_t bf[2] = { __float_as_uint(bv.x), __float_as_uint(bv.y) };
                mma8(d2[0][nt], af[0], bf);
                mma8(d2[1][nt], af[1], bf);
            }
        }
    }

    // ---- epilogue: x = x_mid + D2 + b2 ----
    const float* b2l = f2b + layer * W;
#pragma unroll
    for (int mt = 0; mt < 2; mt++) {
#pragma unroll
        for (int nt = 0; nt < 8; nt++) {
            int col = wn * 64 + nt * 8 + 2 * tig;
            int ra = wm * 32 + mt * 16 + g;
            float2 xm = *(const float2*)&g_x[xbase + (size_t)ra * W + col];
            float2 o;
            o.x = xm.x + d2[mt][nt][0] + b2l[col];
            o.y = xm.y + d2[mt][nt][1] + b2l[col + 1];
            *(float2*)&g_x[xbase + (size_t)ra * W + col] = o;
            int rb = ra + 8;
            float2 xm2 = *(const float2*)&g_x[xbase + (size_t)rb * W + col];
            o.x = xm2.x + d2[mt][nt][2] + b2l[col];
            o.y = xm2.y + d2[mt][nt][3] + b2l[col + 1];
            *(float2*)&g_x[xbase + (size_t)rb * W + col] = o;
        }
    }
}

// ---------------- K5: final projection ----------------
__global__ void __launch_bounds__(256) proj_kernel(
    const float* __restrict__ pw, const float* __restrict__ pb, float* __restrict__ out)
{
    __shared__ float xs[16][W];
    size_t t0 = (size_t)blockIdx.x * 16;
    for (int i = threadIdx.x; i < 16 * W; i += 256)
        xs[i >> 8][i & 255] = g_x[t0 * W + i];
    __syncthreads();
    if (threadIdx.x < 64) {
        int t = threadIdx.x >> 2, o = threadIdx.x & 3;
        float acc = pb[o];
#pragma unroll 8
        for (int c = 0; c < W; c++) acc += xs[t][c] * pw[c * CIN + o];
        out[(t0 + t) * CIN + o] = acc;
    }
}

// ---------------- launch ----------------
extern "C" void kernel_launch(void* const* d_in, const int* in_sizes, int n_in,
                              void* d_out, int out_size)
{
    const float* feat = (const float*)d_in[0];
    const float* coords = (const float*)d_in[1];
    const float* tn   = (const float*)d_in[2];
    const float* ew   = (const float*)d_in[3];
    const float* eb   = (const float*)d_in[4];
    const float* ln1g = (const float*)d_in[5];
    const float* ln1b = (const float*)d_in[6];
    const float* sw   = (const float*)d_in[7];
    const float* sb   = (const float*)d_in[8];
    const float* qkvw = (const float*)d_in[9];
    const float* qkvb = (const float*)d_in[10];
    const float* outw = (const float*)d_in[11];
    const float* outb = (const float*)d_in[12];
    const float* ln2g = (const float*)d_in[13];
    const float* ln2b = (const float*)d_in[14];
    const float* f1w  = (const float*)d_in[15];
    const float* f1b  = (const float*)d_in[16];
    const float* f2w  = (const float*)d_in[17];
    const float* f2b  = (const float*)d_in[18];
    const float* pw   = (const float*)d_in[19];
    const float* pb   = (const float*)d_in[20];

    static int attr_set = 0;
    if (!attr_set) {
        cudaFuncSetAttribute(ffn_mma_kernel, cudaFuncAttributeMaxDynamicSharedMemorySize, SM_FFN_BYTES);
        cudaFuncSetAttribute(latent_kernel, cudaFuncAttributeMaxDynamicSharedMemorySize, LAT_SMEM);
        attr_set = 1;
    }

    embed_kernel<<<B * N / 16, 256>>>(feat, coords, tn, ew, eb);
    w1t_kernel<<<L * FF * W / 256, 256>>>(f1w);
    w2t_zero_kernel<<<NB_W2T + NB_Z + 1, 256>>>(f2w);

    for (int l = 0; l < L; l++) {
        slice_kernel<<<B * (N / TOK1), 256>>>(ln1g, ln1b, sw, sb, l);
        latent_kernel<<<B, 512, LAT_SMEM>>>(qkvw, qkvb, outw, outb, l);
        ffn_mma_kernel<<<B * (N / TOKF), 512, SM_FFN_BYTES>>>(ln2g, ln2b, f1b, f2b, l);
    }

    proj_kernel<<<(B * N) / 16, 256>>>(pw, pb, (float*)d_out);
}

// round 8
// speedup vs baseline: 1.5349x; 1.5349x over previous
#include <cuda_runtime.h>
#include <math.h>
#include <stdint.h>

#define B    4
#define N    16384
#define CIN  4
#define SD   3
#define W    256
#define L    8
#define M    32
#define H    8
#define FF   1024
#define TF   4
#define DH   32
#define TOK1 32
#define TOKF 128
#define JC2  64            // FF chunk width in ffn v2

__device__ float g_x[(size_t)B * N * W];
__device__ float g_w[(size_t)B * N * M];
__device__ float g_z[(size_t)L * B * M * W];
__device__ float g_wsum[L * B * M];
__device__ float g_qkv[B * M * 3 * W];
__device__ float g_o[B * M * W];
__device__ float g_zp[B * M * W];
__device__ float g_w1t[(size_t)L * FF * W];      // [L][FF][Wperm] tf32
__device__ float g_w2t[(size_t)L * W * FF];      // [L][W][FFperm] tf32

// ---------- helpers ----------
__device__ __forceinline__ float to_tf32(float x) {
    uint32_t r; asm("cvt.rna.tf32.f32 %0, %1;" : "=r"(r) : "f"(x));
    return __uint_as_float(r);
}
__device__ __forceinline__ int kperm(int k) {
    return (k & ~7) | ((k & 3) << 1) | ((k >> 2) & 1);
}
// logical-k swizzle (applies within-8 permute + 8-block XOR by row)
__device__ __forceinline__ int swz(int r, int k, int S) {
    return r * S + ((((k >> 3) ^ (r & 7)) << 3) | ((k & 3) << 1) | ((k >> 2) & 1));
}
// identity-low-bits swizzle (source already permuted): only 8-block XOR
__device__ __forceinline__ int bswz(int r, int k, int S) {
    return r * S + ((((k >> 3) ^ (r & 7)) << 3) | (k & 7));
}
__device__ __forceinline__ void mma8(float* d, const uint32_t* a, const uint32_t* b) {
    asm volatile("mma.sync.aligned.m16n8k8.row.col.f32.tf32.tf32.f32 "
        "{%0,%1,%2,%3}, {%4,%5,%6,%7}, {%8,%9}, {%0,%1,%2,%3};"
        : "+f"(d[0]), "+f"(d[1]), "+f"(d[2]), "+f"(d[3])
        : "r"(a[0]), "r"(a[1]), "r"(a[2]), "r"(a[3]), "r"(b[0]), "r"(b[1]));
}

// ---------------- K0: embed (16 tokens / block) ----------------
__global__ void __launch_bounds__(256) embed_kernel(
    const float* __restrict__ feat, const float* __restrict__ coords,
    const float* __restrict__ tn, const float* __restrict__ ew, const float* __restrict__ eb)
{
    __shared__ float f[16][16];
    int t0 = blockIdx.x * 16;
    int tid = threadIdx.x;
    {
        int t = tid >> 4, k = tid & 15;
        int token = t0 + t, b = token / N;
        float v = 0.f;
        if (k < CIN) v = feat[(size_t)token * CIN + k];
        else if (k < CIN + SD) v = coords[(size_t)token * SD + (k - CIN)];
        else if (k < 15) {
            int kk = k - 7, i = kk & 3;
            float ang = powf(1000.0f, -(float)i / (float)TF) * (tn[b] * 1000.0f);
            v = (kk < TF) ? sinf(ang) : cosf(ang);
        }
        f[t][k] = v;
    }
    __syncthreads();
    int c = tid;
    float wreg[15];
#pragma unroll
    for (int k = 0; k < 15; k++) wreg[k] = ew[k * W + c];
    float bias = eb[c];
#pragma unroll 4
    for (int t = 0; t < 16; t++) {
        float acc = bias;
#pragma unroll
        for (int k = 0; k < 15; k++) acc += f[t][k] * wreg[k];
        g_x[(size_t)(t0 + t) * W + c] = acc;
    }
}

// ---------------- weight transform + zero (fused) ----------------
__global__ void __launch_bounds__(256) w1t_kernel(const float* __restrict__ f1w)
{
    int idx = blockIdx.x * 256 + threadIdx.x;            // L*FF*W
    int l = idx / (FF * W), r = idx % (FF * W), j = r / W, c = r % W;
    g_w1t[((size_t)l * FF + j) * W + kperm(c)] =
        to_tf32(f1w[((size_t)l * W + c) * FF + j]);
}
#define NB_W2T (L * W * FF / 256)
#define NB_Z   (L * B * M * W / 256)
__global__ void __launch_bounds__(256) w2t_zero_kernel(const float* __restrict__ f2w)
{
    int bid = blockIdx.x;
    if (bid < NB_W2T) {
        int idx = bid * 256 + threadIdx.x;
        int l = idx / (W * FF), r = idx % (W * FF), c = r / FF, j = r % FF;
        g_w2t[((size_t)l * W + c) * FF + kperm(j)] =
            to_tf32(f2w[((size_t)l * FF + j) * W + c]);
    } else if (bid < NB_W2T + NB_Z) {
        int idx = (bid - NB_W2T) * 256 + threadIdx.x;
        g_z[idx] = 0.f;
    } else {
        for (int i = threadIdx.x; i < L * B * M; i += 256) g_wsum[i] = 0.f;
    }
}

// ---------------- K1: slice ----------------
__global__ void __launch_bounds__(256) slice_kernel(
    const float* __restrict__ ln_g, const float* __restrict__ ln_b,
    const float* __restrict__ sw, const float* __restrict__ sb, int layer)
{
    __shared__ float hs[TOK1][W];
    __shared__ float ws[TOK1][M];
    __shared__ float inv[TOK1];
    int nb = N / TOK1, b = blockIdx.x / nb, t0 = (blockIdx.x % nb) * TOK1;
    int tid = threadIdx.x, warp = tid >> 5, lane = tid & 31;
    const float* g = ln_g + layer * W;
    const float* be = ln_b + layer * W;
    float* zdst = g_z + (size_t)layer * B * M * W;
    float* wsdst = g_wsum + layer * B * M;

    for (int t = warp; t < TOK1; t += 8) {
        const float* xr = g_x + ((size_t)(b * N + t0 + t)) * W;
        float v[8]; float s = 0.f, s2 = 0.f;
#pragma unroll
        for (int i = 0; i < 8; i++) { v[i] = xr[lane + 32 * i]; s += v[i]; s2 += v[i] * v[i]; }
#pragma unroll
        for (int o = 16; o > 0; o >>= 1) {
            s += __shfl_xor_sync(0xffffffffu, s, o);
            s2 += __shfl_xor_sync(0xffffffffu, s2, o);
        }
        float mean = s * (1.0f / W), var = s2 * (1.0f / W) - mean * mean;
        float r = rsqrtf(var + 1e-5f);
#pragma unroll
        for (int i = 0; i < 8; i++) {
            int c = lane + 32 * i;
            hs[t][c] = (v[i] - mean) * r * g[c] + be[c];
        }
    }
    __syncthreads();
    const float* swl = sw + (size_t)layer * W * M;
    float lg[4];
#pragma unroll
    for (int r = 0; r < 4; r++) {
        int idx = tid + 256 * r, t = idx / M, m = idx % M;
        float acc = sb[layer * M + m];
#pragma unroll 8
        for (int c = 0; c < W; c++) acc += hs[t][c] * swl[c * M + m];
        lg[r] = acc;
    }
#pragma unroll
    for (int r = 0; r < 4; r++) { int idx = tid + 256 * r; ws[idx / M][idx % M] = lg[r]; }
    __syncthreads();
    if (tid < TOK1) {
        float mx = -1e30f;
#pragma unroll
        for (int m = 0; m < M; m++) mx = fmaxf(mx, ws[tid][m]);
        float sum = 0.f;
#pragma unroll
        for (int m = 0; m < M; m++) { float e = expf(ws[tid][m] - mx); ws[tid][m] = e; sum += e; }
        inv[tid] = 1.0f / sum;
    }
    __syncthreads();
#pragma unroll
    for (int r = 0; r < 4; r++) {
        int idx = tid + 256 * r, t = idx / M, m = idx % M;
        float v = ws[t][m] * inv[t];
        ws[t][m] = v;
        g_w[((size_t)(b * N + t0 + t)) * M + m] = v;
    }
    __syncthreads();
    if (tid < M) {
        float s = 0.f;
#pragma unroll
        for (int t = 0; t < TOK1; t++) s += ws[t][tid];
        atomicAdd(&wsdst[b * M + tid], s);
    }
    float zacc[M];
#pragma unroll
    for (int m = 0; m < M; m++) zacc[m] = 0.f;
    for (int t = 0; t < TOK1; t++) {
        float hv = hs[t][tid];
#pragma unroll
        for (int m = 0; m < M; m++) zacc[m] += ws[t][m] * hv;
    }
#pragma unroll
    for (int m = 0; m < M; m++) atomicAdd(&zdst[(b * M + m) * W + tid], zacc[m]);
}

// ---------------- K2a/b/c (separate, proven fast) ----------------
__global__ void __launch_bounds__(256) qkv_kernel(
    const float* __restrict__ qkvw, const float* __restrict__ qkvb, int layer)
{
    int b = blockIdx.x / M, m = blockIdx.x % M;
    __shared__ float zs[W];
    float wsv = fmaxf(g_wsum[layer * B * M + b * M + m], 1e-8f);
    zs[threadIdx.x] = g_z[(size_t)layer * B * M * W + (size_t)(b * M + m) * W + threadIdx.x] / wsv;
    __syncthreads();
    const float* wq = qkvw + (size_t)layer * W * 3 * W;
#pragma unroll
    for (int r = 0; r < 3; r++) {
        int j = threadIdx.x + 256 * r;
        float acc = qkvb[layer * 3 * W + j];
#pragma unroll 8
        for (int c = 0; c < W; c++) acc += zs[c] * wq[(size_t)c * (3 * W) + j];
        g_qkv[(size_t)(b * M + m) * (3 * W) + j] = acc;
    }
}
__global__ void __launch_bounds__(256) attn_kernel()
{
    int b = blockIdx.x / H, h = blockIdx.x % H;
    __shared__ float q[M][DH], k[M][DH], v[M][DH], a[M][M];
    int tid = threadIdx.x;
    for (int i = tid; i < M * DH; i += 256) {
        int m = i / DH, d = i % DH;
        const float* base = g_qkv + (size_t)(b * M + m) * (3 * W);
        q[m][d] = base[h * DH + d];
        k[m][d] = base[W + h * DH + d];
        v[m][d] = base[2 * W + h * DH + d];
    }
    __syncthreads();
    const float scale = 0.17677669529663687f;
    for (int i = tid; i < M * M; i += 256) {
        int m = i / M, n2 = i % M;
        float acc = 0.f;
#pragma unroll
        for (int d = 0; d < DH; d++) acc += q[m][d] * k[n2][d];
        a[m][n2] = acc * scale;
    }
    __syncthreads();
    if (tid < M) {
        float mx = -1e30f;
#pragma unroll
        for (int n2 = 0; n2 < M; n2++) mx = fmaxf(mx, a[tid][n2]);
        float s = 0.f;
#pragma unroll
        for (int n2 = 0; n2 < M; n2++) { float e = expf(a[tid][n2] - mx); a[tid][n2] = e; s += e; }
        float is = 1.0f / s;
#pragma unroll
        for (int n2 = 0; n2 < M; n2++) a[tid][n2] *= is;
    }
    __syncthreads();
    for (int i = tid; i < M * DH; i += 256) {
        int m = i / DH, d = i % DH;
        float acc = 0.f;
#pragma unroll
        for (int n2 = 0; n2 < M; n2++) acc += a[m][n2] * v[n2][d];
        g_o[(size_t)(b * M + m) * W + h * DH + d] = acc;
    }
}
__global__ void __launch_bounds__(256) zp_kernel(
    const float* __restrict__ ow, const float* __restrict__ ob, int layer)
{
    int b = blockIdx.x / M, m = blockIdx.x % M;
    __shared__ float os[W];
    os[threadIdx.x] = g_o[(size_t)(b * M + m) * W + threadIdx.x];
    __syncthreads();
    const float* wl = ow + (size_t)layer * W * W;
    float acc = ob[layer * W + threadIdx.x];
#pragma unroll 8
    for (int k2 = 0; k2 < W; k2++) acc += os[k2] * wl[(size_t)k2 * W + threadIdx.x];
    g_zp[(size_t)(b * M + m) * W + threadIdx.x] = acc;
}

// ---------------- K3: FFN v2 — mma.sync tf32, smem-staged weights ---------
// smem floats: s_h2[0,32768) s_g[32768,40960) s_b[40960,57344)  (224 KB)
#define SMO_G  (TOKF * 256)                 // 32768
#define SMO_B  (SMO_G + TOKF * JC2)         // 40960
#define SM_FFN_BYTES ((SMO_B + JC2 * 256) * 4)   // 229376

__global__ void __launch_bounds__(512, 1) ffn_mma_kernel(
    const float* __restrict__ ln2g, const float* __restrict__ ln2b,
    const float* __restrict__ f1b, const float* __restrict__ f2b, int layer)
{
    extern __shared__ float sm[];
    float* s_h2 = sm;
    float* s_g  = sm + SMO_G;
    float* s_b  = sm + SMO_B;
    int tid = threadIdx.x;
    int warp = tid >> 5, lane = tid & 31, g = lane >> 2, tig = lane & 3;
    int nb = N / TOKF, b = blockIdx.x / nb, t0 = (blockIdx.x % nb) * TOKF;
    size_t xbase = ((size_t)(b * N) + t0) * W;

    // ---- prologue: x_mid = x + w@zp ----
    int c = tid & 255, half = tid >> 8;
    float zpc[M];
#pragma unroll
    for (int m = 0; m < M; m++) zpc[m] = g_zp[(size_t)(b * M + m) * W + c];
    for (int i = tid; i < TOKF * M; i += 512)
        s_g[i] = g_w[((size_t)(b * N) + t0 + i / M) * M + (i % M)];
    __syncthreads();
    for (int t = half * 64; t < half * 64 + 64; t++) {
        float acc = g_x[xbase + (size_t)t * W + c];
#pragma unroll
        for (int m = 0; m < M; m++) acc += s_g[t * M + m] * zpc[m];
        g_x[xbase + (size_t)t * W + c] = acc;
        s_h2[swz(t, c, 256)] = acc;
    }
    __syncthreads();

    // ---- LN2 in place (tf32-rounded) ----
    {
        const float* g2 = ln2g + layer * W;
        const float* b2 = ln2b + layer * W;
        for (int rr = 0; rr < 8; rr++) {
            int r = warp * 8 + rr;
            float v[8]; float s = 0.f, s2 = 0.f;
#pragma unroll
            for (int i = 0; i < 8; i++) {
                v[i] = s_h2[swz(r, lane + 32 * i, 256)];
                s += v[i]; s2 += v[i] * v[i];
            }
#pragma unroll
            for (int o = 16; o > 0; o >>= 1) {
                s += __shfl_xor_sync(0xffffffffu, s, o);
                s2 += __shfl_xor_sync(0xffffffffu, s2, o);
            }
            float mean = s * (1.0f / W), var = s2 * (1.0f / W) - mean * mean;
            float rs = rsqrtf(var + 1e-5f);
#pragma unroll
            for (int i = 0; i < 8; i++) {
                int cc = lane + 32 * i;
                s_h2[swz(r, cc, 256)] = to_tf32((v[i] - mean) * rs * g2[cc] + b2[cc]);
            }
        }
    }

    const float* w1l = g_w1t + (size_t)layer * FF * W;
    const float* w2l = g_w2t + (size_t)layer * W * FF;
    const float* b1l = f1b + layer * FF;

    int wm = warp >> 2, wn = warp & 3;       // 4x4 warp grid
    float d2[2][8][4];
#pragma unroll
    for (int mt = 0; mt < 2; mt++)
#pragma unroll
        for (int nt = 0; nt < 8; nt++)
#pragma unroll
            for (int q = 0; q < 4; q++) d2[mt][nt][q] = 0.f;

    for (int chunk = 0; chunk < 16; chunk++) {
        int j0 = chunk * JC2;

        __syncthreads();    // prev GEMM2 / LN2 done before s_b overwrite
        // ---- stage B1 = W1T[j0..j0+64)[0..256) (64 KB, coalesced) ----
#pragma unroll
        for (int it = 0; it < 8; it++) {
            int idx = it * 512 + tid;               // 4096 float4
            int jl = idx >> 6, c4 = (idx & 63) << 2;
            float4 v = *(const float4*)&w1l[(size_t)(j0 + jl) * W + c4];
            *(float4*)&s_b[bswz(jl, c4, 256)] = v;
        }
        __syncthreads();

        // ===== GEMM1: D1[128x64] = h2 @ B1, K=256 =====
        float d1[2][2][4];
#pragma unroll
        for (int mt = 0; mt < 2; mt++)
#pragma unroll
            for (int nt = 0; nt < 2; nt++)
#pragma unroll
                for (int q = 0; q < 4; q++) d1[mt][nt][q] = 0.f;

#pragma unroll 4
        for (int ks = 0; ks < 32; ks++) {
            int kx = ((ks ^ g) << 3) + 2 * tig;
            uint32_t af[2][4];
#pragma unroll
            for (int mt = 0; mt < 2; mt++) {
                int r0 = wm * 32 + mt * 16 + g;
                float2 v0 = *(const float2*)&s_h2[r0 * 256 + kx];
                float2 v1 = *(const float2*)&s_h2[(r0 + 8) * 256 + kx];
                af[mt][0] = __float_as_uint(v0.x);
                af[mt][1] = __float_as_uint(v1.x);
                af[mt][2] = __float_as_uint(v0.y);
                af[mt][3] = __float_as_uint(v1.y);
            }
#pragma unroll
            for (int nt = 0; nt < 2; nt++) {
                int jl = wn * 16 + nt * 8 + g;
                float2 bv = *(const float2*)&s_b[jl * 256 + kx];
                uint32_t bf[2] = { __float_as_uint(bv.x), __float_as_uint(bv.y) };
                mma8(d1[0][nt], af[0], bf);
                mma8(d1[1][nt], af[1], bf);
            }
        }
        __syncthreads();    // GEMM1 reads of s_b done; prev GEMM2 reads of s_g done

        // ---- gelu -> s_g ; stage B2 = W2T[0..256)[j0..j0+64) -> s_b ----
#pragma unroll
        for (int mt = 0; mt < 2; mt++) {
#pragma unroll
            for (int nt = 0; nt < 2; nt++) {
                int row = wm * 32 + mt * 16 + g;
                int jc = wn * 16 + nt * 8 + 2 * tig;
#pragma unroll
                for (int q = 0; q < 4; q++) {
                    int rr = row + (q >> 1) * 8;
                    int jj = jc + (q & 1);
                    float x = d1[mt][nt][q] + b1l[j0 + jj];
                    float gl = 0.5f * x * (1.0f + erff(x * 0.7071067811865476f));
                    s_g[swz(rr, jj, JC2)] = to_tf32(gl);
                }
            }
        }
#pragma unroll
        for (int it = 0; it < 8; it++) {
            int idx = it * 512 + tid;               // 4096 float4
            int cc = idx >> 4, k4 = (idx & 15) << 2;
            float4 v = *(const float4*)&w2l[(size_t)cc * FF + j0 + k4];
            *(float4*)&s_b[bswz(cc, k4, JC2)] = v;
        }
        __syncthreads();

        // ===== GEMM2 partial: D2[128x256] += G @ B2, K=64 =====
#pragma unroll
        for (int ks = 0; ks < 8; ks++) {
            int kx = ((ks ^ g) << 3) + 2 * tig;
            uint32_t af[2][4];
#pragma unroll
            for (int mt = 0; mt < 2; mt++) {
                int r0 = wm * 32 + mt * 16 + g;
                float2 v0 = *(const float2*)&s_g[r0 * JC2 + kx];
                float2 v1 = *(const float2*)&s_g[(r0 + 8) * JC2 + kx];
                af[mt][0] = __float_as_uint(v0.x);
                af[mt][1] = __float_as_uint(v1.x);
                af[mt][2] = __float_as_uint(v0.y);
                af[mt][3] = __float_as_uint(v1.y);
            }
#pragma unroll
            for (int nt = 0; nt < 8; nt++) {
                int cc = wn * 64 + nt * 8 + g;
                float2 bv = *(const float2*)&s_b[cc * JC2 + kx];
                uint32_t bf[2] = { __float_as_uint(bv.x), __float_as_uint(bv.y) };
                mma8(d2[0][nt], af[0], bf);
                mma8(d2[1][nt], af[1], bf);
            }
        }
    }

    // ---- epilogue: x = x_mid + D2 + b2 ----
    const float* b2l = f2b + layer * W;
#pragma unroll
    for (int mt = 0; mt < 2; mt++) {
#pragma unroll
        for (int nt = 0; nt < 8; nt++) {
            int col = wn * 64 + nt * 8 + 2 * tig;
            int ra = wm * 32 + mt * 16 + g;
            float2 xm = *(const float2*)&g_x[xbase + (size_t)ra * W + col];
            float2 o;
            o.x = xm.x + d2[mt][nt][0] + b2l[col];
            o.y = xm.y + d2[mt][nt][1] + b2l[col + 1];
            *(float2*)&g_x[xbase + (size_t)ra * W + col] = o;
            int rb = ra + 8;
            float2 xm2 = *(const float2*)&g_x[xbase + (size_t)rb * W + col];
            o.x = xm2.x + d2[mt][nt][2] + b2l[col];
            o.y = xm2.y + d2[mt][nt][3] + b2l[col + 1];
            *(float2*)&g_x[xbase + (size_t)rb * W + col] = o;
        }
    }
}

// ---------------- K5: final projection ----------------
__global__ void __launch_bounds__(256) proj_kernel(
    const float* __restrict__ pw, const float* __restrict__ pb, float* __restrict__ out)
{
    __shared__ float xs[16][W];
    size_t t0 = (size_t)blockIdx.x * 16;
    for (int i = threadIdx.x; i < 16 * W; i += 256)
        xs[i >> 8][i & 255] = g_x[t0 * W + i];
    __syncthreads();
    if (threadIdx.x < 64) {
        int t = threadIdx.x >> 2, o = threadIdx.x & 3;
        float acc = pb[o];
#pragma unroll 8
        for (int c = 0; c < W; c++) acc += xs[t][c] * pw[c * CIN + o];
        out[(t0 + t) * CIN + o] = acc;
    }
}

// ---------------- launch ----------------
extern "C" void kernel_launch(void* const* d_in, const int* in_sizes, int n_in,
                              void* d_out, int out_size)
{
    const float* feat = (const float*)d_in[0];
    const float* coords = (const float*)d_in[1];
    const float* tn   = (const float*)d_in[2];
    const float* ew   = (const float*)d_in[3];
    const float* eb   = (const float*)d_in[4];
    const float* ln1g = (const float*)d_in[5];
    const float* ln1b = (const float*)d_in[6];
    const float* sw   = (const float*)d_in[7];
    const float* sb   = (const float*)d_in[8];
    const float* qkvw = (const float*)d_in[9];
    const float* qkvb = (const float*)d_in[10];
    const float* outw = (const float*)d_in[11];
    const float* outb = (const float*)d_in[12];
    const float* ln2g = (const float*)d_in[13];
    const float* ln2b = (const float*)d_in[14];
    const float* f1w  = (const float*)d_in[15];
    const float* f1b  = (const float*)d_in[16];
    const float* f2w  = (const float*)d_in[17];
    const float* f2b  = (const float*)d_in[18];
    const float* pw   = (const float*)d_in[19];
    const float* pb   = (const float*)d_in[20];

    static int attr_set = 0;
    if (!attr_set) {
        cudaFuncSetAttribute(ffn_mma_kernel, cudaFuncAttributeMaxDynamicSharedMemorySize, SM_FFN_BYTES);
        attr_set = 1;
    }

    embed_kernel<<<B * N / 16, 256>>>(feat, coords, tn, ew, eb);
    w1t_kernel<<<L * FF * W / 256, 256>>>(f1w);
    w2t_zero_kernel<<<NB_W2T + NB_Z + 1, 256>>>(f2w);

    for (int l = 0; l < L; l++) {
        slice_kernel<<<B * (N / TOK1), 256>>>(ln1g, ln1b, sw, sb, l);
        qkv_kernel<<<B * M, 256>>>(qkvw, qkvb, l);
        attn_kernel<<<B * H, 256>>>();
        zp_kernel<<<B * M, 256>>>(outw, outb, l);
        ffn_mma_kernel<<<B * (N / TOKF), 512, SM_FFN_BYTES>>>(ln2g, ln2b, f1b, f2b, l);
    }

    proj_kernel<<<(B * N) / 16, 256>>>(pw, pb, (float*)d_out);
}

// round 9
// speedup vs baseline: 2.1244x; 1.3841x over previous
#include <cuda_runtime.h>
#include <cuda_fp16.h>
#include <math.h>
#include <stdint.h>

#define B    4
#define N    16384
#define CIN  4
#define SD   3
#define W    256
#define L    8
#define M    32
#define H    8
#define FF   1024
#define TF   4
#define DH   32
#define TOK1 32
#define TOKF 128
#define JC2  64

__device__ float g_x[(size_t)B * N * W];
__device__ float g_w[(size_t)B * N * M];
__device__ float g_z[(size_t)L * B * M * W];
__device__ float g_wsum[L * B * M];
__device__ float g_qkv[B * M * 3 * W];
__device__ float g_o[B * M * W];
__device__ float g_zp[B * M * W];
__device__ __half g_w1t[(size_t)L * FF * W];      // [L][FF][W] fp16
__device__ __half g_w2t[(size_t)L * W * FF];      // [L][W][FF] fp16

// ---------- helpers ----------
// word-index swizzles: XOR word-col by (row&7)<<2 -> conflict-free frags
__device__ __forceinline__ int hw2(int r, int wc) { return r * 128 + (wc ^ ((r & 7) << 2)); }  // 128 words/row
__device__ __forceinline__ int gw2(int r, int wc) { return r * 32  + (wc ^ ((r & 7) << 2)); }  // 32 words/row
__device__ __forceinline__ void mma16(float* d, const uint32_t* a, const uint32_t* b) {
    asm volatile("mma.sync.aligned.m16n8k16.row.col.f32.f16.f16.f32 "
        "{%0,%1,%2,%3}, {%4,%5,%6,%7}, {%8,%9}, {%0,%1,%2,%3};"
        : "+f"(d[0]), "+f"(d[1]), "+f"(d[2]), "+f"(d[3])
        : "r"(a[0]), "r"(a[1]), "r"(a[2]), "r"(a[3]), "r"(b[0]), "r"(b[1]));
}

// ---------------- K0: embed (16 tokens / block) ----------------
__global__ void __launch_bounds__(256) embed_kernel(
    const float* __restrict__ feat, const float* __restrict__ coords,
    const float* __restrict__ tn, const float* __restrict__ ew, const float* __restrict__ eb)
{
    __shared__ float f[16][16];
    int t0 = blockIdx.x * 16;
    int tid = threadIdx.x;
    {
        int t = tid >> 4, k = tid & 15;
        int token = t0 + t, b = token / N;
        float v = 0.f;
        if (k < CIN) v = feat[(size_t)token * CIN + k];
        else if (k < CIN + SD) v = coords[(size_t)token * SD + (k - CIN)];
        else if (k < 15) {
            int kk = k - 7, i = kk & 3;
            float ang = powf(1000.0f, -(float)i / (float)TF) * (tn[b] * 1000.0f);
            v = (kk < TF) ? sinf(ang) : cosf(ang);
        }
        f[t][k] = v;
    }
    __syncthreads();
    int c = tid;
    float wreg[15];
#pragma unroll
    for (int k = 0; k < 15; k++) wreg[k] = ew[k * W + c];
    float bias = eb[c];
#pragma unroll 4
    for (int t = 0; t < 16; t++) {
        float acc = bias;
#pragma unroll
        for (int k = 0; k < 15; k++) acc += f[t][k] * wreg[k];
        g_x[(size_t)(t0 + t) * W + c] = acc;
    }
}

// ---------------- weight transform + zero (fused) ----------------
__global__ void __launch_bounds__(256) w1t_kernel(const float* __restrict__ f1w)
{
    int idx = blockIdx.x * 256 + threadIdx.x;            // L*FF*W
    int l = idx / (FF * W), r = idx % (FF * W), j = r / W, c = r % W;
    g_w1t[((size_t)l * FF + j) * W + c] =
        __float2half(f1w[((size_t)l * W + c) * FF + j]);
}
#define NB_W2T (L * W * FF / 256)
#define NB_Z   (L * B * M * W / 256)
__global__ void __launch_bounds__(256) w2t_zero_kernel(const float* __restrict__ f2w)
{
    int bid = blockIdx.x;
    if (bid < NB_W2T) {
        int idx = bid * 256 + threadIdx.x;
        int l = idx / (W * FF), r = idx % (W * FF), c = r / FF, j = r % FF;
        g_w2t[((size_t)l * W + c) * FF + j] =
            __float2half(f2w[((size_t)l * FF + j) * W + c]);
    } else if (bid < NB_W2T + NB_Z) {
        int idx = (bid - NB_W2T) * 256 + threadIdx.x;
        g_z[idx] = 0.f;
    } else {
        for (int i = threadIdx.x; i < L * B * M; i += 256) g_wsum[i] = 0.f;
    }
}

// ---------------- K1: slice ----------------
__global__ void __launch_bounds__(256) slice_kernel(
    const float* __restrict__ ln_g, const float* __restrict__ ln_b,
    const float* __restrict__ sw, const float* __restrict__ sb, int layer)
{
    __shared__ float hs[TOK1][W];
    __shared__ float ws[TOK1][M];
    __shared__ float inv[TOK1];
    int nb = N / TOK1, b = blockIdx.x / nb, t0 = (blockIdx.x % nb) * TOK1;
    int tid = threadIdx.x, warp = tid >> 5, lane = tid & 31;
    const float* g = ln_g + layer * W;
    const float* be = ln_b + layer * W;
    float* zdst = g_z + (size_t)layer * B * M * W;
    float* wsdst = g_wsum + layer * B * M;

    for (int t = warp; t < TOK1; t += 8) {
        const float* xr = g_x + ((size_t)(b * N + t0 + t)) * W;
        float v[8]; float s = 0.f, s2 = 0.f;
#pragma unroll
        for (int i = 0; i < 8; i++) { v[i] = xr[lane + 32 * i]; s += v[i]; s2 += v[i] * v[i]; }
#pragma unroll
        for (int o = 16; o > 0; o >>= 1) {
            s += __shfl_xor_sync(0xffffffffu, s, o);
            s2 += __shfl_xor_sync(0xffffffffu, s2, o);
        }
        float mean = s * (1.0f / W), var = s2 * (1.0f / W) - mean * mean;
        float r = rsqrtf(var + 1e-5f);
#pragma unroll
        for (int i = 0; i < 8; i++) {
            int c = lane + 32 * i;
            hs[t][c] = (v[i] - mean) * r * g[c] + be[c];
        }
    }
    __syncthreads();
    const float* swl = sw + (size_t)layer * W * M;
    float lg[4];
#pragma unroll
    for (int r = 0; r < 4; r++) {
        int idx = tid + 256 * r, t = idx / M, m = idx % M;
        float acc = sb[layer * M + m];
#pragma unroll 8
        for (int c = 0; c < W; c++) acc += hs[t][c] * swl[c * M + m];
        lg[r] = acc;
    }
#pragma unroll
    for (int r = 0; r < 4; r++) { int idx = tid + 256 * r; ws[idx / M][idx % M] = lg[r]; }
    __syncthreads();
    if (tid < TOK1) {
        float mx = -1e30f;
#pragma unroll
        for (int m = 0; m < M; m++) mx = fmaxf(mx, ws[tid][m]);
        float sum = 0.f;
#pragma unroll
        for (int m = 0; m < M; m++) { float e = expf(ws[tid][m] - mx); ws[tid][m] = e; sum += e; }
        inv[tid] = 1.0f / sum;
    }
    __syncthreads();
#pragma unroll
    for (int r = 0; r < 4; r++) {
        int idx = tid + 256 * r, t = idx / M, m = idx % M;
        float v = ws[t][m] * inv[t];
        ws[t][m] = v;
        g_w[((size_t)(b * N + t0 + t)) * M + m] = v;
    }
    __syncthreads();
    if (tid < M) {
        float s = 0.f;
#pragma unroll
        for (int t = 0; t < TOK1; t++) s += ws[t][tid];
        atomicAdd(&wsdst[b * M + tid], s);
    }
    float zacc[M];
#pragma unroll
    for (int m = 0; m < M; m++) zacc[m] = 0.f;
    for (int t = 0; t < TOK1; t++) {
        float hv = hs[t][tid];
#pragma unroll
        for (int m = 0; m < M; m++) zacc[m] += ws[t][m] * hv;
    }
#pragma unroll
    for (int m = 0; m < M; m++) atomicAdd(&zdst[(b * M + m) * W + tid], zacc[m]);
}

// ---------------- K2a/b/c ----------------
__global__ void __launch_bounds__(256) qkv_kernel(
    const float* __restrict__ qkvw, const float* __restrict__ qkvb, int layer)
{
    int b = blockIdx.x / M, m = blockIdx.x % M;
    __shared__ float zs[W];
    float wsv = fmaxf(g_wsum[layer * B * M + b * M + m], 1e-8f);
    zs[threadIdx.x] = g_z[(size_t)layer * B * M * W + (size_t)(b * M + m) * W + threadIdx.x] / wsv;
    __syncthreads();
    const float* wq = qkvw + (size_t)layer * W * 3 * W;
#pragma unroll
    for (int r = 0; r < 3; r++) {
        int j = threadIdx.x + 256 * r;
        float acc = qkvb[layer * 3 * W + j];
#pragma unroll 8
        for (int c = 0; c < W; c++) acc += zs[c] * wq[(size_t)c * (3 * W) + j];
        g_qkv[(size_t)(b * M + m) * (3 * W) + j] = acc;
    }
}
__global__ void __launch_bounds__(256) attn_kernel()
{
    int b = blockIdx.x / H, h = blockIdx.x % H;
    __shared__ float q[M][DH], k[M][DH], v[M][DH], a[M][M];
    int tid = threadIdx.x;
    for (int i = tid; i < M * DH; i += 256) {
        int m = i / DH, d = i % DH;
        const float* base = g_qkv + (size_t)(b * M + m) * (3 * W);
        q[m][d] = base[h * DH + d];
        k[m][d] = base[W + h * DH + d];
        v[m][d] = base[2 * W + h * DH + d];
    }
    __syncthreads();
    const float scale = 0.17677669529663687f;
    for (int i = tid; i < M * M; i += 256) {
        int m = i / M, n2 = i % M;
        float acc = 0.f;
#pragma unroll
        for (int d = 0; d < DH; d++) acc += q[m][d] * k[n2][d];
        a[m][n2] = acc * scale;
    }
    __syncthreads();
    if (tid < M) {
        float mx = -1e30f;
#pragma unroll
        for (int n2 = 0; n2 < M; n2++) mx = fmaxf(mx, a[tid][n2]);
        float s = 0.f;
#pragma unroll
        for (int n2 = 0; n2 < M; n2++) { float e = expf(a[tid][n2] - mx); a[tid][n2] = e; s += e; }
        float is = 1.0f / s;
#pragma unroll
        for (int n2 = 0; n2 < M; n2++) a[tid][n2] *= is;
    }
    __syncthreads();
    for (int i = tid; i < M * DH; i += 256) {
        int m = i / DH, d = i % DH;
        float acc = 0.f;
#pragma unroll
        for (int n2 = 0; n2 < M; n2++) acc += a[m][n2] * v[n2][d];
        g_o[(size_t)(b * M + m) * W + h * DH + d] = acc;
    }
}
__global__ void __launch_bounds__(256) zp_kernel(
    const float* __restrict__ ow, const float* __restrict__ ob, int layer)
{
    int b = blockIdx.x / M, m = blockIdx.x % M;
    __shared__ float os[W];
    os[threadIdx.x] = g_o[(size_t)(b * M + m) * W + threadIdx.x];
    __syncthreads();
    const float* wl = ow + (size_t)layer * W * W;
    float acc = ob[layer * W + threadIdx.x];
#pragma unroll 8
    for (int k2 = 0; k2 < W; k2++) acc += os[k2] * wl[(size_t)k2 * W + threadIdx.x];
    g_zp[(size_t)(b * M + m) * W + threadIdx.x] = acc;
}

// ---------------- K3: FFN v3 — fp16 m16n8k16, smem-staged weights ---------
// smem (32-bit words): u_h2[0,16384) u_g[16384,20480) u_b[20480,28672)  == 112 KB
#define WO_G 16384
#define WO_B 20480
#define SM_FFN_BYTES (28672 * 4)

__global__ void __launch_bounds__(512, 1) ffn_mma_kernel(
    const float* __restrict__ ln2g, const float* __restrict__ ln2b,
    const float* __restrict__ f1b, const float* __restrict__ f2b, int layer)
{
    extern __shared__ uint32_t usm[];
    uint32_t* u_h2 = usm;                // h2 fp16 [128 rows][128 words]
    uint32_t* u_g  = usm + WO_G;         // G  fp16 [128 rows][32 words]
    uint32_t* u_b  = usm + WO_B;         // B buffer (B1: [64][128] / B2: [256][32])
    __half* h_h2 = (__half*)u_h2;
    int tid = threadIdx.x;
    int warp = tid >> 5, lane = tid & 31, g = lane >> 2, tig = lane & 3;
    int nb = N / TOKF, b = blockIdx.x / nb, t0 = (blockIdx.x % nb) * TOKF;
    size_t xbase = ((size_t)(b * N) + t0) * W;

    // ---- prologue: x_mid = x + w@zp (w tile staged in u_g as float) ----
    int c = tid & 255, half_ = tid >> 8;
    float zpc[M];
#pragma unroll
    for (int m = 0; m < M; m++) zpc[m] = g_zp[(size_t)(b * M + m) * W + c];
    {
        float* s_w = (float*)u_g;        // 4096 floats
        for (int i = tid; i < TOKF * M; i += 512)
            s_w[i] = g_w[((size_t)(b * N) + t0 + i / M) * M + (i % M)];
        __syncthreads();
        int wcol = c >> 1, hi = c & 1;
        for (int t = half_ * 64; t < half_ * 64 + 64; t++) {
            float acc = g_x[xbase + (size_t)t * W + c];
#pragma unroll
            for (int m = 0; m < M; m++) acc += s_w[t * M + m] * zpc[m];
            g_x[xbase + (size_t)t * W + c] = acc;
            h_h2[(t * 128 + (wcol ^ ((t & 7) << 2))) * 2 + hi] = __float2half(acc);
        }
    }
    __syncthreads();

    // ---- LN2 in place on fp16 h2 (stats in fp32) ----
    {
        const float* g2 = ln2g + layer * W;
        const float* b2 = ln2b + layer * W;
        for (int rr = 0; rr < 16; rr++) {
            int r = (warp << 4) + rr;            // 16 warps x 8 rows = 128
            if (warp >= 8) break;
            ;
        }
        for (int rr = 0; rr < 8; rr++) {
            int r = warp * 8 + rr;
            if (r >= TOKF) break;
            float v[8]; float s = 0.f, s2 = 0.f;
#pragma unroll
            for (int i = 0; i < 8; i++) {
                int ci = lane + 32 * i;
                v[i] = __half2float(h_h2[(r * 128 + ((ci >> 1) ^ ((r & 7) << 2))) * 2 + (ci & 1)]);
                s += v[i]; s2 += v[i] * v[i];
            }
#pragma unroll
            for (int o = 16; o > 0; o >>= 1) {
                s += __shfl_xor_sync(0xffffffffu, s, o);
                s2 += __shfl_xor_sync(0xffffffffu, s2, o);
            }
            float mean = s * (1.0f / W), var = s2 * (1.0f / W) - mean * mean;
            float rs = rsqrtf(var + 1e-5f);
#pragma unroll
            for (int i = 0; i < 8; i++) {
                int ci = lane + 32 * i;
                h_h2[(r * 128 + ((ci >> 1) ^ ((r & 7) << 2))) * 2 + (ci & 1)] =
                    __float2half((v[i] - mean) * rs * g2[ci] + b2[ci]);
            }
        }
    }
    // note: warps 8-15 did rows 64-127 via the same loop (warp*8 covers 0..127)

    const __half* w1l = g_w1t + (size_t)layer * FF * W;
    const __half* w2l = g_w2t + (size_t)layer * W * FF;
    const float* b1l = f1b + layer * FF;

    int wm = warp >> 2, wn = warp & 3;       // 4x4 warp grid
    float d2[2][8][4];
#pragma unroll
    for (int mt = 0; mt < 2; mt++)
#pragma unroll
        for (int nt = 0; nt < 8; nt++)
#pragma unroll
            for (int q = 0; q < 4; q++) d2[mt][nt][q] = 0.f;

    for (int chunk = 0; chunk < 16; chunk++) {
        int j0 = chunk * JC2;

        __syncthreads();
        // ---- stage B1 = W1T[j0..j0+64)[0..256) fp16, 32KB ----
#pragma unroll
        for (int it = 0; it < 4; it++) {
            int idx = it * 512 + tid;               // 2048 uint4 (word-quads)
            int jl = idx >> 5, wc4 = (idx & 31) << 2;
            uint4 v = *(const uint4*)&w1l[(size_t)(j0 + jl) * W + wc4 * 2];
            *(uint4*)&u_b[jl * 128 + (wc4 ^ ((jl & 7) << 2))] = v;
        }
        __syncthreads();

        // ===== GEMM1: D1[128x64] = h2 @ B1, K=256 (16 k-steps) =====
        float d1[2][2][4];
#pragma unroll
        for (int mt = 0; mt < 2; mt++)
#pragma unroll
            for (int nt = 0; nt < 2; nt++)
#pragma unroll
                for (int q = 0; q < 4; q++) d1[mt][nt][q] = 0.f;

#pragma unroll 4
        for (int ks = 0; ks < 16; ks++) {
            int kwb = ks * 8;
            uint32_t af[2][4];
#pragma unroll
            for (int mt = 0; mt < 2; mt++) {
                int r0 = wm * 32 + mt * 16 + g;
                af[mt][0] = u_h2[hw2(r0,     kwb + tig)];
                af[mt][1] = u_h2[hw2(r0 + 8, kwb + tig)];
                af[mt][2] = u_h2[hw2(r0,     kwb + tig + 4)];
                af[mt][3] = u_h2[hw2(r0 + 8, kwb + tig + 4)];
            }
#pragma unroll
            for (int nt = 0; nt < 2; nt++) {
                int jl = wn * 16 + nt * 8 + g;
                uint32_t bf[2];
                bf[0] = u_b[hw2(jl, kwb + tig)];
                bf[1] = u_b[hw2(jl, kwb + tig + 4)];
                mma16(d1[0][nt], af[0], bf);
                mma16(d1[1][nt], af[1], bf);
            }
        }
        __syncthreads();

        // ---- gelu -> u_g (fp16) ; stage B2 = W2T[0..256)[j0..j0+64) ----
#pragma unroll
        for (int mt = 0; mt < 2; mt++) {
#pragma unroll
            for (int nt = 0; nt < 2; nt++) {
                int r0 = wm * 32 + mt * 16 + g;
                int jc = wn * 16 + nt * 8 + 2 * tig;
                int wc = wn * 8 + nt * 4 + tig;
                float x0 = d1[mt][nt][0] + b1l[j0 + jc];
                float x1 = d1[mt][nt][1] + b1l[j0 + jc + 1];
                float x2 = d1[mt][nt][2] + b1l[j0 + jc];
                float x3 = d1[mt][nt][3] + b1l[j0 + jc + 1];
                float g0 = 0.5f * x0 * (1.0f + erff(x0 * 0.7071067811865476f));
                float g1 = 0.5f * x1 * (1.0f + erff(x1 * 0.7071067811865476f));
                float g2v = 0.5f * x2 * (1.0f + erff(x2 * 0.7071067811865476f));
                float g3 = 0.5f * x3 * (1.0f + erff(x3 * 0.7071067811865476f));
                __half2 p0 = __floats2half2_rn(g0, g1);
                __half2 p1 = __floats2half2_rn(g2v, g3);
                u_g[gw2(r0,     wc)] = *(uint32_t*)&p0;
                u_g[gw2(r0 + 8, wc)] = *(uint32_t*)&p1;
            }
        }
#pragma unroll
        for (int it = 0; it < 4; it++) {
            int idx = it * 512 + tid;               // 2048 uint4
            int cc = idx >> 3, wc4 = (idx & 7) << 2;
            uint4 v = *(const uint4*)&w2l[(size_t)cc * FF + j0 + wc4 * 2];
            *(uint4*)&u_b[cc * 32 + (wc4 ^ ((cc & 7) << 2))] = v;
        }
        __syncthreads();

        // ===== GEMM2 partial: D2[128x256] += G @ B2, K=64 (4 k-steps) =====
#pragma unroll
        for (int ks = 0; ks < 4; ks++) {
            int kwb = ks * 8;
            uint32_t af[2][4];
#pragma unroll
            for (int mt = 0; mt < 2; mt++) {
                int r0 = wm * 32 + mt * 16 + g;
                af[mt][0] = u_g[gw2(r0,     kwb + tig)];
                af[mt][1] = u_g[gw2(r0 + 8, kwb + tig)];
                af[mt][2] = u_g[gw2(r0,     kwb + tig + 4)];
                af[mt][3] = u_g[gw2(r0 + 8, kwb + tig + 4)];
            }
#pragma unroll
            for (int nt = 0; nt < 8; nt++) {
                int cc = wn * 64 + nt * 8 + g;
                uint32_t bf[2];
                bf[0] = u_b[gw2(cc, kwb + tig)];
                bf[1] = u_b[gw2(cc, kwb + tig + 4)];
                mma16(d2[0][nt], af[0], bf);
                mma16(d2[1][nt], af[1], bf);
            }
        }
    }

    // ---- epilogue: x = x_mid + D2 + b2 ----
    const float* b2l = f2b + layer * W;
#pragma unroll
    for (int mt = 0; mt < 2; mt++) {
#pragma unroll
        for (int nt = 0; nt < 8; nt++) {
            int col = wn * 64 + nt * 8 + 2 * tig;
            int ra = wm * 32 + mt * 16 + g;
            float2 xm = *(const float2*)&g_x[xbase + (size_t)ra * W + col];
            float2 o;
            o.x = xm.x + d2[mt][nt][0] + b2l[col];
            o.y = xm.y + d2[mt][nt][1] + b2l[col + 1];
            *(float2*)&g_x[xbase + (size_t)ra * W + col] = o;
            int rb = ra + 8;
            float2 xm2 = *(const float2*)&g_x[xbase + (size_t)rb * W + col];
            o.x = xm2.x + d2[mt][nt][2] + b2l[col];
            o.y = xm2.y + d2[mt][nt][3] + b2l[col + 1];
            *(float2*)&g_x[xbase + (size_t)rb * W + col] = o;
        }
    }
}

// ---------------- K5: final projection ----------------
__global__ void __launch_bounds__(256) proj_kernel(
    const float* __restrict__ pw, const float* __restrict__ pb, float* __restrict__ out)
{
    __shared__ float xs[16][W];
    size_t t0 = (size_t)blockIdx.x * 16;
    for (int i = threadIdx.x; i < 16 * W; i += 256)
        xs[i >> 8][i & 255] = g_x[t0 * W + i];
    __syncthreads();
    if (threadIdx.x < 64) {
        int t = threadIdx.x >> 2, o = threadIdx.x & 3;
        float acc = pb[o];
#pragma unroll 8
        for (int c = 0; c < W; c++) acc += xs[t][c] * pw[c * CIN + o];
        out[(t0 + t) * CIN + o] = acc;
    }
}

// ---------------- launch ----------------
extern "C" void kernel_launch(void* const* d_in, const int* in_sizes, int n_in,
                              void* d_out, int out_size)
{
    const float* feat = (const float*)d_in[0];
    const float* coords = (const float*)d_in[1];
    const float* tn   = (const float*)d_in[2];
    const float* ew   = (const float*)d_in[3];
    const float* eb   = (const float*)d_in[4];
    const float* ln1g = (const float*)d_in[5];
    const float* ln1b = (const float*)d_in[6];
    const float* sw   = (const float*)d_in[7];
    const float* sb   = (const float*)d_in[8];
    const float* qkvw = (const float*)d_in[9];
    const float* qkvb = (const float*)d_in[10];
    const float* outw = (const float*)d_in[11];
    const float* outb = (const float*)d_in[12];
    const float* ln2g = (const float*)d_in[13];
    const float* ln2b = (const float*)d_in[14];
    const float* f1w  = (const float*)d_in[15];
    const float* f1b  = (const float*)d_in[16];
    const float* f2w  = (const float*)d_in[17];
    const float* f2b  = (const float*)d_in[18];
    const float* pw   = (const float*)d_in[19];
    const float* pb   = (const float*)d_in[20];

    static int attr_set = 0;
    if (!attr_set) {
        cudaFuncSetAttribute(ffn_mma_kernel, cudaFuncAttributeMaxDynamicSharedMemorySize, SM_FFN_BYTES);
        attr_set = 1;
    }

    embed_kernel<<<B * N / 16, 256>>>(feat, coords, tn, ew, eb);
    w1t_kernel<<<L * FF * W / 256, 256>>>(f1w);
    w2t_zero_kernel<<<NB_W2T + NB_Z + 1, 256>>>(f2w);

    for (int l = 0; l < L; l++) {
        slice_kernel<<<B * (N / TOK1), 256>>>(ln1g, ln1b, sw, sb, l);
        qkv_kernel<<<B * M, 256>>>(qkvw, qkvb, l);
        attn_kernel<<<B * H, 256>>>();
        zp_kernel<<<B * M, 256>>>(outw, outb, l);
        ffn_mma_kernel<<<B * (N / TOKF), 512, SM_FFN_BYTES>>>(ln2g, ln2b, f1b, f2b, l);
    }

    proj_kernel<<<(B * N) / 16, 256>>>(pw, pb, (float*)d_out);
}

// round 10
// speedup vs baseline: 2.2954x; 1.0805x over previous
#include <cuda_runtime.h>
#include <cuda_fp16.h>
#include <math.h>
#include <stdint.h>

#define B    4
#define N    16384
#define CIN  4
#define SD   3
#define W    256
#define L    8
#define M    32
#define H    8
#define FF   1024
#define TF   4
#define DH   32
#define TOK1 32
#define TOKF 128
#define JC2  64

__device__ float g_x[(size_t)B * N * W];
__device__ float g_w[(size_t)B * N * M];
__device__ float g_z[(size_t)L * B * M * W];
__device__ float g_wsum[L * B * M];
__device__ float g_qkv[B * M * 3 * W];
__device__ float g_o[B * M * W];
__device__ float g_zp[B * M * W];
__device__ __half g_w1t[(size_t)L * FF * W];      // [L][FF][W] fp16
__device__ __half g_w2t[(size_t)L * W * FF];      // [L][W][FF] fp16

// ---------- helpers ----------
__device__ __forceinline__ int hw2(int r, int wc) { return r * 128 + (wc ^ ((r & 7) << 2)); }
__device__ __forceinline__ int gw2(int r, int wc) { return r * 32  + (wc ^ ((r & 7) << 2)); }
__device__ __forceinline__ void mma16(float* d, const uint32_t* a, const uint32_t* b) {
    asm volatile("mma.sync.aligned.m16n8k16.row.col.f32.f16.f16.f32 "
        "{%0,%1,%2,%3}, {%4,%5,%6,%7}, {%8,%9}, {%0,%1,%2,%3};"
        : "+f"(d[0]), "+f"(d[1]), "+f"(d[2]), "+f"(d[3])
        : "r"(a[0]), "r"(a[1]), "r"(a[2]), "r"(a[3]), "r"(b[0]), "r"(b[1]));
}

// ---------------- K0: embed (16 tokens / block) ----------------
__global__ void __launch_bounds__(256) embed_kernel(
    const float* __restrict__ feat, const float* __restrict__ coords,
    const float* __restrict__ tn, const float* __restrict__ ew, const float* __restrict__ eb)
{
    __shared__ float f[16][16];
    int t0 = blockIdx.x * 16;
    int tid = threadIdx.x;
    {
        int t = tid >> 4, k = tid & 15;
        int token = t0 + t, b = token / N;
        float v = 0.f;
        if (k < CIN) v = feat[(size_t)token * CIN + k];
        else if (k < CIN + SD) v = coords[(size_t)token * SD + (k - CIN)];
        else if (k < 15) {
            int kk = k - 7, i = kk & 3;
            float ang = powf(1000.0f, -(float)i / (float)TF) * (tn[b] * 1000.0f);
            v = (kk < TF) ? sinf(ang) : cosf(ang);
        }
        f[t][k] = v;
    }
    __syncthreads();
    int c = tid;
    float wreg[15];
#pragma unroll
    for (int k = 0; k < 15; k++) wreg[k] = ew[k * W + c];
    float bias = eb[c];
#pragma unroll 4
    for (int t = 0; t < 16; t++) {
        float acc = bias;
#pragma unroll
        for (int k = 0; k < 15; k++) acc += f[t][k] * wreg[k];
        g_x[(size_t)(t0 + t) * W + c] = acc;
    }
}

// ---------------- weight transform + zero (fused) ----------------
__global__ void __launch_bounds__(256) w1t_kernel(const float* __restrict__ f1w)
{
    int idx = blockIdx.x * 256 + threadIdx.x;
    int l = idx / (FF * W), r = idx % (FF * W), j = r / W, c = r % W;
    g_w1t[((size_t)l * FF + j) * W + c] =
        __float2half(f1w[((size_t)l * W + c) * FF + j]);
}
#define NB_W2T (L * W * FF / 256)
#define NB_Z   (L * B * M * W / 256)
__global__ void __launch_bounds__(256) w2t_zero_kernel(const float* __restrict__ f2w)
{
    int bid = blockIdx.x;
    if (bid < NB_W2T) {
        int idx = bid * 256 + threadIdx.x;
        int l = idx / (W * FF), r = idx % (W * FF), c = r / FF, j = r % FF;
        g_w2t[((size_t)l * W + c) * FF + j] =
            __float2half(f2w[((size_t)l * FF + j) * W + c]);
    } else if (bid < NB_W2T + NB_Z) {
        int idx = (bid - NB_W2T) * 256 + threadIdx.x;
        g_z[idx] = 0.f;
    } else {
        for (int i = threadIdx.x; i < L * B * M; i += 256) g_wsum[i] = 0.f;
    }
}

// ---------------- K1: slice (vectorized loads) ----------------
__global__ void __launch_bounds__(256) slice_kernel(
    const float* __restrict__ ln_g, const float* __restrict__ ln_b,
    const float* __restrict__ sw, const float* __restrict__ sb, int layer)
{
    __shared__ float hs[TOK1][W];
    __shared__ float ws[TOK1][M];
    __shared__ float inv[TOK1];
    int nb = N / TOK1, b = blockIdx.x / nb, t0 = (blockIdx.x % nb) * TOK1;
    int tid = threadIdx.x, warp = tid >> 5, lane = tid & 31;
    const float* g = ln_g + layer * W;
    const float* be = ln_b + layer * W;
    float* zdst = g_z + (size_t)layer * B * M * W;
    float* wsdst = g_wsum + layer * B * M;

    // LayerNorm: 8 warps x 4 tokens
    for (int t = warp; t < TOK1; t += 8) {
        const float* xr = g_x + ((size_t)(b * N + t0 + t)) * W;
        float v[8]; float s = 0.f, s2 = 0.f;
#pragma unroll
        for (int i = 0; i < 8; i++) { v[i] = xr[lane + 32 * i]; s += v[i]; s2 += v[i] * v[i]; }
#pragma unroll
        for (int o = 16; o > 0; o >>= 1) {
            s += __shfl_xor_sync(0xffffffffu, s, o);
            s2 += __shfl_xor_sync(0xffffffffu, s2, o);
        }
        float mean = s * (1.0f / W), var = s2 * (1.0f / W) - mean * mean;
        float r = rsqrtf(var + 1e-5f);
#pragma unroll
        for (int i = 0; i < 8; i++) {
            int c = lane + 32 * i;
            hs[t][c] = (v[i] - mean) * r * g[c] + be[c];
        }
    }
    __syncthreads();

    // logits: thread -> (t = tid>>3, 4 m's); LDG.128 weights
    const float* swl = sw + (size_t)layer * W * M;
    {
        int t = tid >> 3, m4 = (tid & 7) << 2;
        float4 acc = *(const float4*)&sb[layer * M + m4];
#pragma unroll 8
        for (int c = 0; c < W; c++) {
            float hv = hs[t][c];
            float4 sv = *(const float4*)&swl[c * M + m4];
            acc.x += hv * sv.x; acc.y += hv * sv.y;
            acc.z += hv * sv.z; acc.w += hv * sv.w;
        }
        *(float4*)&ws[t][m4] = acc;
    }
    __syncthreads();

    // softmax over M per token (32 threads)
    if (tid < TOK1) {
        float mx = -1e30f;
#pragma unroll
        for (int m = 0; m < M; m++) mx = fmaxf(mx, ws[tid][m]);
        float sum = 0.f;
#pragma unroll
        for (int m = 0; m < M; m++) { float e = expf(ws[tid][m] - mx); ws[tid][m] = e; sum += e; }
        inv[tid] = 1.0f / sum;
    }
    __syncthreads();

    // normalize + write w (float4)
    {
        int t = tid >> 3, m4 = (tid & 7) << 2;
        float iv = inv[t];
        float4 v = *(const float4*)&ws[t][m4];
        v.x *= iv; v.y *= iv; v.z *= iv; v.w *= iv;
        *(float4*)&ws[t][m4] = v;
        *(float4*)&g_w[((size_t)(b * N + t0 + t)) * M + m4] = v;
    }
    __syncthreads();

    // wsum partials
    if (tid < M) {
        float s = 0.f;
#pragma unroll
        for (int t = 0; t < TOK1; t++) s += ws[t][tid];
        atomicAdd(&wsdst[b * M + tid], s);
    }

    // z accumulation: thread owns channel c = tid; ws via LDS.128 broadcast
    float zacc[M];
#pragma unroll
    for (int m = 0; m < M; m++) zacc[m] = 0.f;
    for (int t = 0; t < TOK1; t++) {
        float hv = hs[t][tid];
#pragma unroll
        for (int mq = 0; mq < 8; mq++) {
            float4 wv = *(const float4*)&ws[t][mq << 2];
            zacc[(mq << 2) + 0] += wv.x * hv;
            zacc[(mq << 2) + 1] += wv.y * hv;
            zacc[(mq << 2) + 2] += wv.z * hv;
            zacc[(mq << 2) + 3] += wv.w * hv;
        }
    }
#pragma unroll
    for (int m = 0; m < M; m++) atomicAdd(&zdst[(b * M + m) * W + tid], zacc[m]);
}

// ---------------- K2a: qkv (768 threads, one j each) ----------------
__global__ void __launch_bounds__(768) qkv_kernel(
    const float* __restrict__ qkvw, const float* __restrict__ qkvb, int layer)
{
    int b = blockIdx.x / M, m = blockIdx.x % M;
    __shared__ float zs[W];
    int tid = threadIdx.x;
    if (tid < W) {
        float wsv = fmaxf(g_wsum[layer * B * M + b * M + m], 1e-8f);
        zs[tid] = g_z[(size_t)layer * B * M * W + (size_t)(b * M + m) * W + tid] / wsv;
    }
    __syncthreads();
    const float* wq = qkvw + (size_t)layer * W * 3 * W;
    float acc = qkvb[layer * 3 * W + tid];
#pragma unroll 8
    for (int c = 0; c < W; c++) acc += zs[c] * wq[(size_t)c * (3 * W) + tid];
    g_qkv[(size_t)(b * M + m) * (3 * W) + tid] = acc;
}

__global__ void __launch_bounds__(256) attn_kernel()
{
    int b = blockIdx.x / H, h = blockIdx.x % H;
    __shared__ float q[M][DH], k[M][DH], v[M][DH], a[M][M];
    int tid = threadIdx.x;
    for (int i = tid; i < M * DH; i += 256) {
        int m = i / DH, d = i % DH;
        const float* base = g_qkv + (size_t)(b * M + m) * (3 * W);
        q[m][d] = base[h * DH + d];
        k[m][d] = base[W + h * DH + d];
        v[m][d] = base[2 * W + h * DH + d];
    }
    __syncthreads();
    const float scale = 0.17677669529663687f;
    for (int i = tid; i < M * M; i += 256) {
        int m = i / M, n2 = i % M;
        float acc = 0.f;
#pragma unroll
        for (int d = 0; d < DH; d++) acc += q[m][d] * k[n2][d];
        a[m][n2] = acc * scale;
    }
    __syncthreads();
    if (tid < M) {
        float mx = -1e30f;
#pragma unroll
        for (int n2 = 0; n2 < M; n2++) mx = fmaxf(mx, a[tid][n2]);
        float s = 0.f;
#pragma unroll
        for (int n2 = 0; n2 < M; n2++) { float e = expf(a[tid][n2] - mx); a[tid][n2] = e; s += e; }
        float is = 1.0f / s;
#pragma unroll
        for (int n2 = 0; n2 < M; n2++) a[tid][n2] *= is;
    }
    __syncthreads();
    for (int i = tid; i < M * DH; i += 256) {
        int m = i / DH, d = i % DH;
        float acc = 0.f;
#pragma unroll
        for (int n2 = 0; n2 < M; n2++) acc += a[m][n2] * v[n2][d];
        g_o[(size_t)(b * M + m) * W + h * DH + d] = acc;
    }
}
__global__ void __launch_bounds__(256) zp_kernel(
    const float* __restrict__ ow, const float* __restrict__ ob, int layer)
{
    int b = blockIdx.x / M, m = blockIdx.x % M;
    __shared__ float os[W];
    os[threadIdx.x] = g_o[(size_t)(b * M + m) * W + threadIdx.x];
    __syncthreads();
    const float* wl = ow + (size_t)layer * W * W;
    float acc = ob[layer * W + threadIdx.x];
#pragma unroll 8
    for (int k2 = 0; k2 < W; k2++) acc += os[k2] * wl[(size_t)k2 * W + threadIdx.x];
    g_zp[(size_t)(b * M + m) * W + threadIdx.x] = acc;
}

// ---------------- K3: FFN fp16 m16n8k16 (unchanged from R9) ----------------
#define WO_G 16384
#define WO_B 20480
#define SM_FFN_BYTES (28672 * 4)

__global__ void __launch_bounds__(512, 1) ffn_mma_kernel(
    const float* __restrict__ ln2g, const float* __restrict__ ln2b,
    const float* __restrict__ f1b, const float* __restrict__ f2b, int layer)
{
    extern __shared__ uint32_t usm[];
    uint32_t* u_h2 = usm;
    uint32_t* u_g  = usm + WO_G;
    uint32_t* u_b  = usm + WO_B;
    __half* h_h2 = (__half*)u_h2;
    int tid = threadIdx.x;
    int warp = tid >> 5, lane = tid & 31, g = lane >> 2, tig = lane & 3;
    int nb = N / TOKF, b = blockIdx.x / nb, t0 = (blockIdx.x % nb) * TOKF;
    size_t xbase = ((size_t)(b * N) + t0) * W;

    int c = tid & 255, half_ = tid >> 8;
    float zpc[M];
#pragma unroll
    for (int m = 0; m < M; m++) zpc[m] = g_zp[(size_t)(b * M + m) * W + c];
    {
        float* s_w = (float*)u_g;
        for (int i = tid; i < TOKF * M; i += 512)
            s_w[i] = g_w[((size_t)(b * N) + t0 + i / M) * M + (i % M)];
        __syncthreads();
        int wcol = c >> 1, hi = c & 1;
        for (int t = half_ * 64; t < half_ * 64 + 64; t++) {
            float acc = g_x[xbase + (size_t)t * W + c];
#pragma unroll
            for (int m = 0; m < M; m++) acc += s_w[t * M + m] * zpc[m];
            g_x[xbase + (size_t)t * W + c] = acc;
            h_h2[(t * 128 + (wcol ^ ((t & 7) << 2))) * 2 + hi] = __float2half(acc);
        }
    }
    __syncthreads();

    {
        const float* g2 = ln2g + layer * W;
        const float* b2 = ln2b + layer * W;
        for (int rr = 0; rr < 8; rr++) {
            int r = warp * 8 + rr;
            if (r >= TOKF) break;
            float v[8]; float s = 0.f, s2 = 0.f;
#pragma unroll
            for (int i = 0; i < 8; i++) {
                int ci = lane + 32 * i;
                v[i] = __half2float(h_h2[(r * 128 + ((ci >> 1) ^ ((r & 7) << 2))) * 2 + (ci & 1)]);
                s += v[i]; s2 += v[i] * v[i];
            }
#pragma unroll
            for (int o = 16; o > 0; o >>= 1) {
                s += __shfl_xor_sync(0xffffffffu, s, o);
                s2 += __shfl_xor_sync(0xffffffffu, s2, o);
            }
            float mean = s * (1.0f / W), var = s2 * (1.0f / W) - mean * mean;
            float rs = rsqrtf(var + 1e-5f);
#pragma unroll
            for (int i = 0; i < 8; i++) {
                int ci = lane + 32 * i;
                h_h2[(r * 128 + ((ci >> 1) ^ ((r & 7) << 2))) * 2 + (ci & 1)] =
                    __float2half((v[i] - mean) * rs * g2[ci] + b2[ci]);
            }
        }
    }

    const __half* w1l = g_w1t + (size_t)layer * FF * W;
    const __half* w2l = g_w2t + (size_t)layer * W * FF;
    const float* b1l = f1b + layer * FF;

    int wm = warp >> 2, wn = warp & 3;
    float d2[2][8][4];
#pragma unroll
    for (int mt = 0; mt < 2; mt++)
#pragma unroll
        for (int nt = 0; nt < 8; nt++)
#pragma unroll
            for (int q = 0; q < 4; q++) d2[mt][nt][q] = 0.f;

    for (int chunk = 0; chunk < 16; chunk++) {
        int j0 = chunk * JC2;

        __syncthreads();
#pragma unroll
        for (int it = 0; it < 4; it++) {
            int idx = it * 512 + tid;
            int jl = idx >> 5, wc4 = (idx & 31) << 2;
            uint4 v = *(const uint4*)&w1l[(size_t)(j0 + jl) * W + wc4 * 2];
            *(uint4*)&u_b[jl * 128 + (wc4 ^ ((jl & 7) << 2))] = v;
        }
        __syncthreads();

        float d1[2][2][4];
#pragma unroll
        for (int mt = 0; mt < 2; mt++)
#pragma unroll
            for (int nt = 0; nt < 2; nt++)
#pragma unroll
                for (int q = 0; q < 4; q++) d1[mt][nt][q] = 0.f;

#pragma unroll 4
        for (int ks = 0; ks < 16; ks++) {
            int kwb = ks * 8;
            uint32_t af[2][4];
#pragma unroll
            for (int mt = 0; mt < 2; mt++) {
                int r0 = wm * 32 + mt * 16 + g;
                af[mt][0] = u_h2[hw2(r0,     kwb + tig)];
                af[mt][1] = u_h2[hw2(r0 + 8, kwb + tig)];
                af[mt][2] = u_h2[hw2(r0,     kwb + tig + 4)];
                af[mt][3] = u_h2[hw2(r0 + 8, kwb + tig + 4)];
            }
#pragma unroll
            for (int nt = 0; nt < 2; nt++) {
                int jl = wn * 16 + nt * 8 + g;
                uint32_t bf[2];
                bf[0] = u_b[hw2(jl, kwb + tig)];
                bf[1] = u_b[hw2(jl, kwb + tig + 4)];
                mma16(d1[0][nt], af[0], bf);
                mma16(d1[1][nt], af[1], bf);
            }
        }
        __syncthreads();

#pragma unroll
        for (int mt = 0; mt < 2; mt++) {
#pragma unroll
            for (int nt = 0; nt < 2; nt++) {
                int r0 = wm * 32 + mt * 16 + g;
                int jc = wn * 16 + nt * 8 + 2 * tig;
                int wc = wn * 8 + nt * 4 + tig;
                float x0 = d1[mt][nt][0] + b1l[j0 + jc];
                float x1 = d1[mt][nt][1] + b1l[j0 + jc + 1];
                float x2 = d1[mt][nt][2] + b1l[j0 + jc];
                float x3 = d1[mt][nt][3] + b1l[j0 + jc + 1];
                float g0 = 0.5f * x0 * (1.0f + erff(x0 * 0.7071067811865476f));
                float g1 = 0.5f * x1 * (1.0f + erff(x1 * 0.7071067811865476f));
                float g2v = 0.5f * x2 * (1.0f + erff(x2 * 0.7071067811865476f));
                float g3 = 0.5f * x3 * (1.0f + erff(x3 * 0.7071067811865476f));
                __half2 p0 = __floats2half2_rn(g0, g1);
                __half2 p1 = __floats2half2_rn(g2v, g3);
                u_g[gw2(r0,     wc)] = *(uint32_t*)&p0;
                u_g[gw2(r0 + 8, wc)] = *(uint32_t*)&p1;
            }
        }
#pragma unroll
        for (int it = 0; it < 4; it++) {
            int idx = it * 512 + tid;
            int cc = idx >> 3, wc4 = (idx & 7) << 2;
            uint4 v = *(const uint4*)&w2l[(size_t)cc * FF + j0 + wc4 * 2];
            *(uint4*)&u_b[cc * 32 + (wc4 ^ ((cc & 7) << 2))] = v;
        }
        __syncthreads();

#pragma unroll
        for (int ks = 0; ks < 4; ks++) {
            int kwb = ks * 8;
            uint32_t af[2][4];
#pragma unroll
            for (int mt = 0; mt < 2; mt++) {
                int r0 = wm * 32 + mt * 16 + g;
                af[mt][0] = u_g[gw2(r0,     kwb + tig)];
                af[mt][1] = u_g[gw2(r0 + 8, kwb + tig)];
                af[mt][2] = u_g[gw2(r0,     kwb + tig + 4)];
                af[mt][3] = u_g[gw2(r0 + 8, kwb + tig + 4)];
            }
#pragma unroll
            for (int nt = 0; nt < 8; nt++) {
                int cc = wn * 64 + nt * 8 + g;
                uint32_t bf[2];
                bf[0] = u_b[gw2(cc, kwb + tig)];
                bf[1] = u_b[gw2(cc, kwb + tig + 4)];
                mma16(d2[0][nt], af[0], bf);
                mma16(d2[1][nt], af[1], bf);
            }
        }
    }

    const float* b2l = f2b + layer * W;
#pragma unroll
    for (int mt = 0; mt < 2; mt++) {
#pragma unroll
        for (int nt = 0; nt < 8; nt++) {
            int col = wn * 64 + nt * 8 + 2 * tig;
            int ra = wm * 32 + mt * 16 + g;
            float2 xm = *(const float2*)&g_x[xbase + (size_t)ra * W + col];
            float2 o;
            o.x = xm.x + d2[mt][nt][0] + b2l[col];
            o.y = xm.y + d2[mt][nt][1] + b2l[col + 1];
            *(float2*)&g_x[xbase + (size_t)ra * W + col] = o;
            int rb = ra + 8;
            float2 xm2 = *(const float2*)&g_x[xbase + (size_t)rb * W + col];
            o.x = xm2.x + d2[mt][nt][2] + b2l[col];
            o.y = xm2.y + d2[mt][nt][3] + b2l[col + 1];
            *(float2*)&g_x[xbase + (size_t)rb * W + col] = o;
        }
    }
}

// ---------------- K5: final projection ----------------
__global__ void __launch_bounds__(256) proj_kernel(
    const float* __restrict__ pw, const float* __restrict__ pb, float* __restrict__ out)
{
    __shared__ float xs[16][W];
    size_t t0 = (size_t)blockIdx.x * 16;
    for (int i = threadIdx.x; i < 16 * W; i += 256)
        xs[i >> 8][i & 255] = g_x[t0 * W + i];
    __syncthreads();
    if (threadIdx.x < 64) {
        int t = threadIdx.x >> 2, o = threadIdx.x & 3;
        float acc = pb[o];
#pragma unroll 8
        for (int c = 0; c < W; c++) acc += xs[t][c] * pw[c * CIN + o];
        out[(t0 + t) * CIN + o] = acc;
    }
}

// ---------------- launch ----------------
extern "C" void kernel_launch(void* const* d_in, const int* in_sizes, int n_in,
                              void* d_out, int out_size)
{
    const float* feat = (const float*)d_in[0];
    const float* coords = (const float*)d_in[1];
    const float* tn   = (const float*)d_in[2];
    const float* ew   = (const float*)d_in[3];
    const float* eb   = (const float*)d_in[4];
    const float* ln1g = (const float*)d_in[5];
    const float* ln1b = (const float*)d_in[6];
    const float* sw   = (const float*)d_in[7];
    const float* sb   = (const float*)d_in[8];
    const float* qkvw = (const float*)d_in[9];
    const float* qkvb = (const float*)d_in[10];
    const float* outw = (const float*)d_in[11];
    const float* outb = (const float*)d_in[12];
    const float* ln2g = (const float*)d_in[13];
    const float* ln2b = (const float*)d_in[14];
    const float* f1w  = (const float*)d_in[15];
    const float* f1b  = (const float*)d_in[16];
    const float* f2w  = (const float*)d_in[17];
    const float* f2b  = (const float*)d_in[18];
    const float* pw   = (const float*)d_in[19];
    const float* pb   = (const float*)d_in[20];

    static int attr_set = 0;
    if (!attr_set) {
        cudaFuncSetAttribute(ffn_mma_kernel, cudaFuncAttributeMaxDynamicSharedMemorySize, SM_FFN_BYTES);
        attr_set = 1;
    }

    embed_kernel<<<B * N / 16, 256>>>(feat, coords, tn, ew, eb);
    w1t_kernel<<<L * FF * W / 256, 256>>>(f1w);
    w2t_zero_kernel<<<NB_W2T + NB_Z + 1, 256>>>(f2w);

    for (int l = 0; l < L; l++) {
        slice_kernel<<<B * (N / TOK1), 256>>>(ln1g, ln1b, sw, sb, l);
        qkv_kernel<<<B * M, 768>>>(qkvw, qkvb, l);
        attn_kernel<<<B * H, 256>>>();
        zp_kernel<<<B * M, 256>>>(outw, outb, l);
        ffn_mma_kernel<<<B * (N / TOKF), 512, SM_FFN_BYTES>>>(ln2g, ln2b, f1b, f2b, l);
    }

    proj_kernel<<<(B * N) / 16, 256>>>(pw, pb, (float*)d_out);
}